// round 1
// baseline (speedup 1.0000x reference)
#include <cuda_runtime.h>
#include <math.h>

// ---------------- problem constants ----------------
#define NB     512            // graphs
#define NODES  90             // nodes per graph
#define NTOT   (NB*NODES)     // 46080
#define FIN    90
#define H      128
#define DEG    16
#define EPG    (NODES*DEG)    // 1440 edges per graph
#define E_TOT  (NTOT*DEG)     // 737280
#define ZROW   384            // 3*H, per-node width of concat buffer
#define ZW     (NODES*ZROW)   // 34560 per graph
#define HL     64
#define KSPLIT 18
#define KCH    1920           // 34560/18
#define TK     64

// ---------------- device scratch (static, no allocs) ----------------
__device__ float         g_z[(size_t)NB*ZW];     // concat(h1,h2,h3) layout [g][node][l*128+f]
__device__ float         g_dis[NTOT];
__device__ float         g_csr_norm[E_TOT];
__device__ unsigned char g_csr_src[E_TOT];
__device__ int           g_rowptr[NB*91];
__device__ float         g_part[KSPLIT*NB*HL];
__device__ float         g_hid[NB*HL];

// ---------------- prep: deg -> dis -> CSR(norm, src) per graph ----------------
// Fully deterministic: per-dst-row serial scan (no float atomics).
__global__ __launch_bounds__(256) void prep_kernel(const void* __restrict__ ei_raw,
                                                   const float* __restrict__ attr)
{
    __shared__ float          w_s[EPG];
    __shared__ unsigned short sd_s[EPG];
    __shared__ float          nrm_s[EPG];
    __shared__ unsigned char  src_s[EPG];
    __shared__ int            cnt_s[NODES];
    __shared__ int            rp_s[NODES+1];
    __shared__ float          dis_s[NODES];

    const int g = blockIdx.x, t = threadIdx.x;

    // dtype sniff: int64 edge_index has zero high words at odd int32 slots
    const int* e32 = (const int*)ei_raw;
    const long long* e64 = (const long long*)ei_raw;
    const bool is64 = ((e32[1] | e32[3] | e32[5] | e32[7] |
                        e32[9] | e32[11] | e32[13] | e32[15]) == 0);

    for (int i = t; i < NODES; i += 256) cnt_s[i] = 0;
    __syncthreads();

    const long long base = (long long)g * NODES;
    for (int e = t; e < EPG; e += 256) {
        const int gi = g*EPG + e;
        int s, d;
        if (is64) { s = (int)(e64[gi] - base); d = (int)(e64[E_TOT + gi] - base); }
        else      { s = e32[gi] - (int)base;   d = e32[E_TOT + gi] - (int)base;   }
        w_s[e]  = attr[gi];
        sd_s[e] = (unsigned short)(s | (d << 7));
        atomicAdd(&cnt_s[d], 1);                       // int atomic: count is deterministic
    }
    __syncthreads();

    if (t == 0) {
        int acc = 0;
        for (int i = 0; i < NODES; ++i) { rp_s[i] = acc; acc += cnt_s[i]; }
        rp_s[NODES] = acc;
    }
    __syncthreads();

    if (t < NODES) {                                   // one thread owns one dst row
        const int i = t;
        int off = rp_s[i];
        float deg = 1.0f;                              // self-loop weight 1
        for (int e = 0; e < EPG; ++e) {
            const unsigned short sd = sd_s[e];
            if ((sd >> 7) == i) {
                const float w = w_s[e];
                deg += w;
                nrm_s[off] = w;                        // temp: raw weight
                src_s[off] = (unsigned char)(sd & 127);
                ++off;
            }
        }
        const float dis = rsqrtf(deg);                 // deg >= 1 always
        dis_s[i] = dis;
        g_dis[g*NODES + i] = dis;
    }
    __syncthreads();

    if (t < NODES) {                                   // norm = dis[s]*w*dis[d]
        const int i = t;
        const float di = dis_s[i];
        for (int p = rp_s[i]; p < rp_s[i+1]; ++p)
            nrm_s[p] = dis_s[src_s[p]] * nrm_s[p] * di;
    }
    __syncthreads();

    for (int p = t; p < EPG; p += 256) {
        g_csr_norm[g*EPG + p] = nrm_s[p];
        g_csr_src[g*EPG + p]  = src_s[p];
    }
    for (int i = t; i <= NODES; i += 256) g_rowptr[g*91 + i] = rp_s[i];
}

// ---------------- fused GCNConv layer: GEMM(in@W) + CSR aggregate + bias + relu ----------------
// One CTA per graph. smem: W tile + input tile (rows padded to 96) + h tile + CSR.
template<int F>
__global__ __launch_bounds__(256, 1) void conv_kernel(
    const float* __restrict__ xin, int stride, int col_in,
    const float* __restrict__ W, const float* __restrict__ bias, int col_out)
{
    extern __shared__ float sm[];
    float*         s_W    = sm;                        // F*128
    float*         s_in   = s_W + F*H;                 // 96*F (rows 90..95 zero)
    float*         s_h    = s_in + 96*F;               // 96*128
    float*         s_norm = s_h + 96*H;                // 1440
    float*         s_dis2 = s_norm + EPG;              // 96
    int*           s_rp   = (int*)(s_dis2 + 96);       // 92
    unsigned char* s_src  = (unsigned char*)(s_rp + 92); // 1440

    const int g = blockIdx.x, t = threadIdx.x;
    const float* inbase = xin ? xin : (g_z + col_in);

    { // W -> smem (float4)
        const float4* W4 = (const float4*)W;
        float4* sW4 = (float4*)s_W;
        for (int idx = t; idx < F*H/4; idx += 256) sW4[idx] = W4[idx];
    }
    for (int idx = t; idx < 96*F; idx += 256) {        // input tile, zero-padded rows
        const int i = idx / F, k = idx - i*F;
        s_in[idx] = (i < NODES) ? inbase[(size_t)(g*NODES + i)*stride + k] : 0.f;
    }
    { // CSR -> smem
        const float4* n4 = (const float4*)(g_csr_norm + (size_t)g*EPG);
        float4* sn4 = (float4*)s_norm;
        for (int idx = t; idx < EPG/4; idx += 256) sn4[idx] = n4[idx];
        const int* s4 = (const int*)(g_csr_src + (size_t)g*EPG);
        int* ss4 = (int*)s_src;
        for (int idx = t; idx < EPG/4; idx += 256) ss4[idx] = s4[idx];
    }
    for (int idx = t; idx <= NODES; idx += 256) s_rp[idx] = g_rowptr[g*91 + idx];
    for (int idx = t; idx < NODES; idx += 256) {
        const float d = g_dis[g*NODES + idx];
        s_dis2[idx] = d*d;
    }
    __syncthreads();

    // GEMM h[96][128] = in[96][F] @ W[F][128]; thread tile 12 rows x 4 cols
    {
        const int rg = t >> 5, cg = t & 31;
        float acc[12][4];
        #pragma unroll
        for (int r = 0; r < 12; ++r) acc[r][0]=acc[r][1]=acc[r][2]=acc[r][3]=0.f;
        const float* inb = s_in + rg*12*F;
        #pragma unroll 2
        for (int k = 0; k < F; ++k) {
            const float4 w = ((const float4*)(s_W + k*H))[cg];
            #pragma unroll
            for (int r = 0; r < 12; ++r) {
                const float a = inb[r*F + k];
                acc[r][0] = fmaf(a, w.x, acc[r][0]);
                acc[r][1] = fmaf(a, w.y, acc[r][1]);
                acc[r][2] = fmaf(a, w.z, acc[r][2]);
                acc[r][3] = fmaf(a, w.w, acc[r][3]);
            }
        }
        float4* hout = (float4*)(s_h + rg*12*H) + cg;
        #pragma unroll
        for (int r = 0; r < 12; ++r)
            hout[r*32] = make_float4(acc[r][0], acc[r][1], acc[r][2], acc[r][3]);
    }
    __syncthreads();

    // Aggregation: warp per dst row, lane owns 4 feature cols, accumulator in regs
    {
        const int lane = t & 31, w = t >> 5;
        const float4 bv = ((const float4*)bias)[lane];
        float* zbase = g_z + (size_t)g*ZW + col_out;
        for (int i = w; i < NODES; i += 8) {
            const float4 hv = ((const float4*)(s_h + i*H))[lane];
            const float d2 = s_dis2[i];
            float4 acc = make_float4(d2*hv.x, d2*hv.y, d2*hv.z, d2*hv.w);
            const int pe = s_rp[i+1];
            for (int p = s_rp[i]; p < pe; ++p) {
                const float nm = s_norm[p];
                const int sidx = s_src[p];
                const float4 h2 = ((const float4*)(s_h + sidx*H))[lane];
                acc.x = fmaf(nm, h2.x, acc.x);
                acc.y = fmaf(nm, h2.y, acc.y);
                acc.z = fmaf(nm, h2.z, acc.z);
                acc.w = fmaf(nm, h2.w, acc.w);
            }
            acc.x = fmaxf(acc.x + bv.x, 0.f);
            acc.y = fmaxf(acc.y + bv.y, 0.f);
            acc.z = fmaxf(acc.z + bv.z, 0.f);
            acc.w = fmaxf(acc.w + bv.w, 0.f);
            *(float4*)(zbase + i*ZROW + lane*4) = acc;
        }
    }
}

// ---------------- lin1: [512 x 34560] @ [34560 x 64], K-split x18 ----------------
__global__ __launch_bounds__(128) void lin1_kernel(const float* __restrict__ Wl)
{
    __shared__ float a_s[TK*36];   // k-major, padded row stride 36 (16B aligned)
    __shared__ float b_s[TK*64];

    const int r0 = blockIdx.x * 32;
    const size_t k0 = (size_t)blockIdx.y * KCH;
    const int t = threadIdx.x;
    const int tr = t >> 4, tc = t & 15;

    float acc[4][4];
    #pragma unroll
    for (int u = 0; u < 4; ++u)
        acc[u][0]=acc[u][1]=acc[u][2]=acc[u][3]=0.f;

    for (int kt = 0; kt < KCH; kt += TK) {
        for (int q = t; q < 512; q += 128) {           // a: 32 rows x 64 k (transposed store)
            const int r = q >> 4, kq = (q & 15) * 4;
            const float4 v = *(const float4*)(g_z + (size_t)(r0 + r)*ZW + k0 + kt + kq);
            a_s[(kq+0)*36 + r] = v.x;
            a_s[(kq+1)*36 + r] = v.y;
            a_s[(kq+2)*36 + r] = v.z;
            a_s[(kq+3)*36 + r] = v.w;
        }
        for (int q = t; q < 1024; q += 128) {          // b: 64 k x 64 cols
            const int kk = q >> 4, cq = (q & 15) * 4;
            *(float4*)(b_s + kk*64 + cq) = *(const float4*)(Wl + (k0 + kt + kk)*64 + cq);
        }
        __syncthreads();
        #pragma unroll 8
        for (int kk = 0; kk < TK; ++kk) {
            const float4 av = *(const float4*)(a_s + kk*36 + tr*4);
            const float4 bb = *(const float4*)(b_s + kk*64 + tc*4);
            acc[0][0]=fmaf(av.x,bb.x,acc[0][0]); acc[0][1]=fmaf(av.x,bb.y,acc[0][1]);
            acc[0][2]=fmaf(av.x,bb.z,acc[0][2]); acc[0][3]=fmaf(av.x,bb.w,acc[0][3]);
            acc[1][0]=fmaf(av.y,bb.x,acc[1][0]); acc[1][1]=fmaf(av.y,bb.y,acc[1][1]);
            acc[1][2]=fmaf(av.y,bb.z,acc[1][2]); acc[1][3]=fmaf(av.y,bb.w,acc[1][3]);
            acc[2][0]=fmaf(av.z,bb.x,acc[2][0]); acc[2][1]=fmaf(av.z,bb.y,acc[2][1]);
            acc[2][2]=fmaf(av.z,bb.z,acc[2][2]); acc[2][3]=fmaf(av.z,bb.w,acc[2][3]);
            acc[3][0]=fmaf(av.w,bb.x,acc[3][0]); acc[3][1]=fmaf(av.w,bb.y,acc[3][1]);
            acc[3][2]=fmaf(av.w,bb.z,acc[3][2]); acc[3][3]=fmaf(av.w,bb.w,acc[3][3]);
        }
        __syncthreads();
    }
    float* pout = g_part + ((size_t)blockIdx.y*NB + r0) * HL;
    #pragma unroll
    for (int u = 0; u < 4; ++u)
        *(float4*)(pout + (tr*4+u)*HL + tc*4) =
            make_float4(acc[u][0], acc[u][1], acc[u][2], acc[u][3]);
}

__global__ __launch_bounds__(256) void lin1_reduce(const float* __restrict__ b)
{
    const int idx = blockIdx.x*256 + threadIdx.x;      // < 512*64
    float s = b[idx & 63];
    #pragma unroll
    for (int ks = 0; ks < KSPLIT; ++ks) s += g_part[(size_t)ks*NB*HL + idx];
    g_hid[idx] = fmaxf(s, 0.f);
}

// ---------------- head: hid @ lin2_W + b -> log_softmax ----------------
__global__ __launch_bounds__(64) void head_kernel(const float* __restrict__ W,
                                                  const float* __restrict__ bb,
                                                  float* __restrict__ out)
{
    const int g = blockIdx.x, t = threadIdx.x;
    const float v = g_hid[g*HL + t];
    float p0 = v * W[t*2 + 0];
    float p1 = v * W[t*2 + 1];
    #pragma unroll
    for (int o = 16; o; o >>= 1) {
        p0 += __shfl_down_sync(0xffffffffu, p0, o);
        p1 += __shfl_down_sync(0xffffffffu, p1, o);
    }
    __shared__ float s0[2], s1[2];
    if ((t & 31) == 0) { s0[t>>5] = p0; s1[t>>5] = p1; }
    __syncthreads();
    if (t == 0) {
        const float l0 = s0[0] + s0[1] + bb[0];
        const float l1 = s1[0] + s1[1] + bb[1];
        const float m = fmaxf(l0, l1);
        const float lse = m + logf(expf(l0 - m) + expf(l1 - m));
        out[g*2 + 0] = l0 - lse;
        out[g*2 + 1] = l1 - lse;
    }
}

// ---------------- launch ----------------
static const int SMEM90  = (FIN*H + 96*FIN + 96*H + EPG + 96 + 92) * 4 + EPG; // 137744
static const int SMEM128 = (H*H  + 96*H  + 96*H + EPG + 96 + 92) * 4 + EPG;   // 171792

extern "C" void kernel_launch(void* const* d_in, const int* in_sizes, int n_in,
                              void* d_out, int out_size)
{
    const float* x        = (const float*)d_in[0];
    const float* eattr    = (const float*)d_in[1];
    const float* W1       = (const float*)d_in[2];
    const float* b1       = (const float*)d_in[3];
    const float* W2       = (const float*)d_in[4];
    const float* b2       = (const float*)d_in[5];
    const float* W3       = (const float*)d_in[6];
    const float* b3       = (const float*)d_in[7];
    const float* lin1_W   = (const float*)d_in[8];
    const float* lin1_b   = (const float*)d_in[9];
    const float* lin2_W   = (const float*)d_in[10];
    const float* lin2_b   = (const float*)d_in[11];
    const void*  eindex   = d_in[12];
    float* out = (float*)d_out;

    cudaFuncSetAttribute(conv_kernel<90>,  cudaFuncAttributeMaxDynamicSharedMemorySize, SMEM90);
    cudaFuncSetAttribute(conv_kernel<128>, cudaFuncAttributeMaxDynamicSharedMemorySize, SMEM128);

    prep_kernel<<<NB, 256>>>(eindex, eattr);
    conv_kernel<90> <<<NB, 256, SMEM90 >>>(x,       90,   0, W1, b1,   0);
    conv_kernel<128><<<NB, 256, SMEM128>>>(nullptr, ZROW, 0, W2, b2, 128);
    conv_kernel<128><<<NB, 256, SMEM128>>>(nullptr, ZROW, 128, W3, b3, 256);
    lin1_kernel<<<dim3(16, KSPLIT), 128>>>(lin1_W);
    lin1_reduce<<<NB*HL/256, 256>>>(lin1_b);
    head_kernel<<<NB, 64>>>(lin2_W, lin2_b, out);
}

// round 3
// speedup vs baseline: 1.1024x; 1.1024x over previous
#include <cuda_runtime.h>
#include <math.h>

// ---------------- problem constants ----------------
#define NB     512            // graphs
#define NODES  90             // nodes per graph
#define NTOT   (NB*NODES)     // 46080
#define FIN    90
#define H      128
#define DEG    16
#define EPG    (NODES*DEG)    // 1440 edges per graph
#define E_TOT  (NTOT*DEG)     // 737280
#define ZROW   384            // 3*H, per-node width of concat buffer
#define ZW     (NODES*ZROW)   // 34560 per graph
#define HL     64
#define KSPLIT 36
#define KCH    960            // 34560/36

// ---------------- device scratch (static, no allocs) ----------------
__device__ float         g_z[(size_t)NB*ZW];     // concat(h1,h2,h3) [g][node][l*128+f]
__device__ float         g_dis[NTOT];
__device__ float         g_csr_norm[E_TOT];
__device__ unsigned char g_csr_src[E_TOT];
__device__ int           g_rowptr[NB*91];
__device__ float         g_part[(size_t)KSPLIT*NB*HL];
__device__ float         g_hid[NB*HL];

// ---------------- prep: deg -> dis -> CSR(norm, src) per graph ----------------
__global__ __launch_bounds__(256) void prep_kernel(const void* __restrict__ ei_raw,
                                                   const float* __restrict__ attr)
{
    __shared__ float          w_s[EPG];
    __shared__ unsigned short sd_s[EPG];
    __shared__ float          nrm_s[EPG];
    __shared__ unsigned char  src_s[EPG];
    __shared__ int            cnt_s[NODES];
    __shared__ int            rp_s[NODES+1];
    __shared__ float          dis_s[NODES];

    const int g = blockIdx.x, t = threadIdx.x;

    // dtype sniff: int64 edge_index has zero high words at odd int32 slots
    const int* e32 = (const int*)ei_raw;
    const long long* e64 = (const long long*)ei_raw;
    const bool is64 = ((e32[1] | e32[3] | e32[5] | e32[7] |
                        e32[9] | e32[11] | e32[13] | e32[15]) == 0);

    for (int i = t; i < NODES; i += 256) cnt_s[i] = 0;
    __syncthreads();

    const long long base = (long long)g * NODES;
    for (int e = t; e < EPG; e += 256) {
        const int gi = g*EPG + e;
        int s, d;
        if (is64) { s = (int)(e64[gi] - base); d = (int)(e64[E_TOT + gi] - base); }
        else      { s = e32[gi] - (int)base;   d = e32[E_TOT + gi] - (int)base;   }
        w_s[e]  = attr[gi];
        sd_s[e] = (unsigned short)(s | (d << 7));
        atomicAdd(&cnt_s[d], 1);
    }
    __syncthreads();

    if (t == 0) {
        int acc = 0;
        for (int i = 0; i < NODES; ++i) { rp_s[i] = acc; acc += cnt_s[i]; }
        rp_s[NODES] = acc;
    }
    __syncthreads();

    if (t < NODES) {                                   // one thread owns one dst row
        const int i = t;
        int off = rp_s[i];
        float deg = 1.0f;                              // self-loop weight 1
        for (int e = 0; e < EPG; ++e) {
            const unsigned short sd = sd_s[e];
            if ((sd >> 7) == i) {
                const float w = w_s[e];
                deg += w;
                nrm_s[off] = w;
                src_s[off] = (unsigned char)(sd & 127);
                ++off;
            }
        }
        const float dis = rsqrtf(deg);
        dis_s[i] = dis;
        g_dis[g*NODES + i] = dis;
    }
    __syncthreads();

    if (t < NODES) {
        const int i = t;
        const float di = dis_s[i];
        for (int p = rp_s[i]; p < rp_s[i+1]; ++p)
            nrm_s[p] = dis_s[src_s[p]] * nrm_s[p] * di;
    }
    __syncthreads();

    for (int p = t; p < EPG; p += 256) {
        g_csr_norm[g*EPG + p] = nrm_s[p];
        g_csr_src[g*EPG + p]  = src_s[p];
    }
    for (int i = t; i <= NODES; i += 256) g_rowptr[g*91 + i] = rp_s[i];
}

// ---------------- fused GCNConv, column-split: each CTA does 64 of 128 cols ----------------
// grid = (NB, 2). 2 CTAs/SM resident.
template<int F, int KPAD>
__global__ __launch_bounds__(256, 2) void conv_kernel(
    const float* __restrict__ xin, int stride, int col_in,
    const float* __restrict__ W, const float* __restrict__ bias, int col_out)
{
    extern __shared__ float sm[];
    float*         s_W    = sm;                        // KPAD*64
    float*         s_in   = s_W + KPAD*64;             // 96*KPAD (padded rows/cols zero)
    float*         s_h    = s_in + 96*KPAD;            // 96*64
    float*         s_norm = s_h + 96*64;               // 1440
    float*         s_dis2 = s_norm + EPG;              // 96
    int*           s_rp   = (int*)(s_dis2 + 96);       // 92
    unsigned char* s_src  = (unsigned char*)(s_rp + 92); // 1440

    const int g = blockIdx.x, t = threadIdx.x;
    const int h0 = blockIdx.y * 64;                    // column half

    { // W[:, h0:h0+64] -> smem (float4); zero pad rows [F, KPAD)
        const float4* W4 = (const float4*)W;
        float4* sW4 = (float4*)s_W;
        for (int idx = t; idx < KPAD*16; idx += 256) {
            const int k = idx >> 4, c4 = idx & 15;
            sW4[idx] = (k < F) ? W4[k*32 + (h0 >> 2) + c4]
                               : make_float4(0.f, 0.f, 0.f, 0.f);
        }
    }
    if (F == 128) {                                    // input from g_z, float4 path
        const float4* inb = (const float4*)(g_z + col_in);
        float4* si4 = (float4*)s_in;
        for (int idx = t; idx < 96*32; idx += 256) {
            const int i = idx >> 5, c4 = idx & 31;
            si4[i*(KPAD/4) + c4] = (i < NODES)
                ? inb[((size_t)(g*NODES + i)*stride >> 2) + c4]
                : make_float4(0.f, 0.f, 0.f, 0.f);
        }
    } else {                                           // raw x, scalar, pad to KPAD
        for (int idx = t; idx < 96*KPAD; idx += 256) {
            const int i = idx / KPAD, k = idx - i*KPAD;
            s_in[idx] = (i < NODES && k < F)
                ? xin[(size_t)(g*NODES + i)*stride + k] : 0.f;
        }
    }
    { // CSR -> smem
        const float4* n4 = (const float4*)(g_csr_norm + (size_t)g*EPG);
        float4* sn4 = (float4*)s_norm;
        for (int idx = t; idx < EPG/4; idx += 256) sn4[idx] = n4[idx];
        const int* sg4 = (const int*)(g_csr_src + (size_t)g*EPG);
        int* ss4 = (int*)s_src;
        for (int idx = t; idx < EPG/4; idx += 256) ss4[idx] = sg4[idx];
    }
    for (int idx = t; idx <= NODES; idx += 256) s_rp[idx] = g_rowptr[g*91 + idx];
    for (int idx = t; idx < NODES; idx += 256) {
        const float d = g_dis[g*NODES + idx];
        s_dis2[idx] = d*d;
    }
    __syncthreads();

    // GEMM h[96][64] = in[96][KPAD] @ W[KPAD][64]; thread tile 6 rows x 4 cols
    {
        const int rg = t >> 4, cg = t & 15;            // 16 row-groups x 16 col-groups
        constexpr int K4 = KPAD / 4;
        float acc[6][4];
        #pragma unroll
        for (int r = 0; r < 6; ++r)
            acc[r][0]=acc[r][1]=acc[r][2]=acc[r][3]=0.f;

        const float4* in4 = (const float4*)s_in + rg*6*K4;
        const float4* W4s = (const float4*)s_W;
        #pragma unroll 2
        for (int k4 = 0; k4 < K4; ++k4) {
            float4 a[6];
            #pragma unroll
            for (int r = 0; r < 6; ++r) a[r] = in4[r*K4 + k4];
            #pragma unroll
            for (int j = 0; j < 4; ++j) {
                const float4 w = W4s[(k4*4 + j)*16 + cg];
                #pragma unroll
                for (int r = 0; r < 6; ++r) {
                    const float av = ((const float*)&a[r])[j];
                    acc[r][0] = fmaf(av, w.x, acc[r][0]);
                    acc[r][1] = fmaf(av, w.y, acc[r][1]);
                    acc[r][2] = fmaf(av, w.z, acc[r][2]);
                    acc[r][3] = fmaf(av, w.w, acc[r][3]);
                }
            }
        }
        float4* hout = (float4*)s_h + cg;
        #pragma unroll
        for (int r = 0; r < 6; ++r)
            hout[(rg*6 + r)*16] = make_float4(acc[r][0], acc[r][1], acc[r][2], acc[r][3]);
    }
    __syncthreads();

    // Aggregation: warp per dst row, lane owns 2 cols (float2), acc in regs
    {
        const int lane = t & 31, w = t >> 5;
        const float2 bv = *(const float2*)(bias + h0 + lane*2);
        float* zbase = g_z + (size_t)g*ZW + col_out + h0;
        for (int i = w; i < NODES; i += 8) {
            const float2 hv = *(const float2*)(s_h + i*64 + lane*2);
            const float d2 = s_dis2[i];
            float2 acc = make_float2(d2*hv.x, d2*hv.y);
            const int pe = s_rp[i+1];
            for (int p = s_rp[i]; p < pe; ++p) {
                const float nm = s_norm[p];
                const float2 h2 = *(const float2*)(s_h + (int)s_src[p]*64 + lane*2);
                acc.x = fmaf(nm, h2.x, acc.x);
                acc.y = fmaf(nm, h2.y, acc.y);
            }
            acc.x = fmaxf(acc.x + bv.x, 0.f);
            acc.y = fmaxf(acc.y + bv.y, 0.f);
            *(float2*)(zbase + i*ZROW + lane*2) = acc;
        }
    }
}

// ---------------- lin1: [512 x 34560] @ [34560 x 64], 64x64 tiles, K-split x36 ----------------
__global__ __launch_bounds__(256) void lin1_kernel(const float* __restrict__ Wl)
{
    __shared__ float a_s[64*68];   // k-major, row stride 68 (transposed A tile)
    __shared__ float b_s[64*64];

    const int r0 = blockIdx.x * 64;
    const size_t k0 = (size_t)blockIdx.y * KCH;
    const int t = threadIdx.x;
    const int tr = t >> 4, tc = t & 15;

    float acc[4][4];
    #pragma unroll
    for (int u = 0; u < 4; ++u)
        acc[u][0]=acc[u][1]=acc[u][2]=acc[u][3]=0.f;

    for (int kt = 0; kt < KCH; kt += 64) {
        for (int q = t; q < 1024; q += 256) {          // a: 64 rows x 64 k (transposed)
            const int r = q >> 4, kq = (q & 15) * 4;
            const float4 v = *(const float4*)(g_z + (size_t)(r0 + r)*ZW + k0 + kt + kq);
            a_s[(kq+0)*68 + r] = v.x;
            a_s[(kq+1)*68 + r] = v.y;
            a_s[(kq+2)*68 + r] = v.z;
            a_s[(kq+3)*68 + r] = v.w;
        }
        for (int q = t; q < 1024; q += 256) {          // b: 64 k x 64 cols
            const int kk = q >> 4, cq = (q & 15) * 4;
            *(float4*)(b_s + kk*64 + cq) = *(const float4*)(Wl + (k0 + kt + kk)*64 + cq);
        }
        __syncthreads();
        #pragma unroll 8
        for (int kk = 0; kk < 64; ++kk) {
            const float4 av = *(const float4*)(a_s + kk*68 + tr*4);   // broadcast in warp
            const float4 bb = *(const float4*)(b_s + kk*64 + tc*4);
            acc[0][0]=fmaf(av.x,bb.x,acc[0][0]); acc[0][1]=fmaf(av.x,bb.y,acc[0][1]);
            acc[0][2]=fmaf(av.x,bb.z,acc[0][2]); acc[0][3]=fmaf(av.x,bb.w,acc[0][3]);
            acc[1][0]=fmaf(av.y,bb.x,acc[1][0]); acc[1][1]=fmaf(av.y,bb.y,acc[1][1]);
            acc[1][2]=fmaf(av.y,bb.z,acc[1][2]); acc[1][3]=fmaf(av.y,bb.w,acc[1][3]);
            acc[2][0]=fmaf(av.z,bb.x,acc[2][0]); acc[2][1]=fmaf(av.z,bb.y,acc[2][1]);
            acc[2][2]=fmaf(av.z,bb.z,acc[2][2]); acc[2][3]=fmaf(av.z,bb.w,acc[2][3]);
            acc[3][0]=fmaf(av.w,bb.x,acc[3][0]); acc[3][1]=fmaf(av.w,bb.y,acc[3][1]);
            acc[3][2]=fmaf(av.w,bb.z,acc[3][2]); acc[3][3]=fmaf(av.w,bb.w,acc[3][3]);
        }
        __syncthreads();
    }
    float* pout = g_part + ((size_t)blockIdx.y*NB + r0) * HL;
    #pragma unroll
    for (int u = 0; u < 4; ++u)
        *(float4*)(pout + (tr*4+u)*HL + tc*4) =
            make_float4(acc[u][0], acc[u][1], acc[u][2], acc[u][3]);
}

__global__ __launch_bounds__(256) void lin1_reduce(const float* __restrict__ b)
{
    const int idx = blockIdx.x*256 + threadIdx.x;      // < 512*64
    float s = b[idx & 63];
    #pragma unroll
    for (int ks = 0; ks < KSPLIT; ++ks) s += g_part[(size_t)ks*NB*HL + idx];
    g_hid[idx] = fmaxf(s, 0.f);
}

// ---------------- head: hid @ lin2_W + b -> log_softmax ----------------
__global__ __launch_bounds__(64) void head_kernel(const float* __restrict__ W,
                                                  const float* __restrict__ bb,
                                                  float* __restrict__ out)
{
    const int g = blockIdx.x, t = threadIdx.x;
    const float v = g_hid[g*HL + t];
    float p0 = v * W[t*2 + 0];
    float p1 = v * W[t*2 + 1];
    #pragma unroll
    for (int o = 16; o; o >>= 1) {
        p0 += __shfl_down_sync(0xffffffffu, p0, o);
        p1 += __shfl_down_sync(0xffffffffu, p1, o);
    }
    __shared__ float s0[2], s1[2];
    if ((t & 31) == 0) { s0[t>>5] = p0; s1[t>>5] = p1; }
    __syncthreads();
    if (t == 0) {
        const float l0 = s0[0] + s0[1] + bb[0];
        const float l1 = s1[0] + s1[1] + bb[1];
        const float m = fmaxf(l0, l1);
        const float lse = m + logf(expf(l0 - m) + expf(l1 - m));
        out[g*2 + 0] = l0 - lse;
        out[g*2 + 1] = l1 - lse;
    }
}

// ---------------- launch ----------------
static const int SMEM90  = (92*64  + 96*92  + 96*64 + EPG + 96 + 92) * 4 + EPG; // 91408
static const int SMEM128 = (128*64 + 96*128 + 96*64 + EPG + 96 + 92) * 4 + EPG; // 114448

extern "C" void kernel_launch(void* const* d_in, const int* in_sizes, int n_in,
                              void* d_out, int out_size)
{
    const float* x        = (const float*)d_in[0];
    const float* eattr    = (const float*)d_in[1];
    const float* W1       = (const float*)d_in[2];
    const float* b1       = (const float*)d_in[3];
    const float* W2       = (const float*)d_in[4];
    const float* b2       = (const float*)d_in[5];
    const float* W3       = (const float*)d_in[6];
    const float* b3       = (const float*)d_in[7];
    const float* lin1_W   = (const float*)d_in[8];
    const float* lin1_b   = (const float*)d_in[9];
    const float* lin2_W   = (const float*)d_in[10];
    const float* lin2_b   = (const float*)d_in[11];
    const void*  eindex   = d_in[12];
    float* out = (float*)d_out;

    cudaFuncSetAttribute(conv_kernel<90,92>,   cudaFuncAttributeMaxDynamicSharedMemorySize, SMEM90);
    cudaFuncSetAttribute(conv_kernel<128,128>, cudaFuncAttributeMaxDynamicSharedMemorySize, SMEM128);

    prep_kernel<<<NB, 256>>>(eindex, eattr);
    conv_kernel<90,92>  <<<dim3(NB,2), 256, SMEM90 >>>(x,       90,   0, W1, b1,   0);
    conv_kernel<128,128><<<dim3(NB,2), 256, SMEM128>>>(nullptr, ZROW, 0, W2, b2, 128);
    conv_kernel<128,128><<<dim3(NB,2), 256, SMEM128>>>(nullptr, ZROW, 128, W3, b3, 256);
    lin1_kernel<<<dim3(8, KSPLIT), 256>>>(lin1_W);
    lin1_reduce<<<NB*HL/256, 256>>>(lin1_b);
    head_kernel<<<NB, 64>>>(lin2_W, lin2_b, out);
}

// round 5
// speedup vs baseline: 1.1089x; 1.0059x over previous
#include <cuda_runtime.h>
#include <math.h>

// ---------------- problem constants ----------------
#define NB     512            // graphs
#define NODES  90             // nodes per graph
#define NTOT   (NB*NODES)     // 46080
#define FIN    90
#define H      128
#define DEG    16
#define EPG    (NODES*DEG)    // 1440 edges per graph
#define E_TOT  (NTOT*DEG)     // 737280
#define ZROW   384            // 3*H, per-node width of concat buffer
#define ZW     (NODES*ZROW)   // 34560 per graph
#define HL     64
#define KSPLIT 36
#define KCH    960            // 34560/36

// ---------------- device scratch (static, no allocs) ----------------
__device__ float g_z[(size_t)NB*ZW];        // concat(h1,h2,h3) [g][node][l*128+f]
__device__ float g_adj[(size_t)NB*96*96];   // dense normalized adjacency, zero-padded
__device__ float g_part[(size_t)KSPLIT*NB*HL];
__device__ float g_hid[NB*HL];

// ---------------- prep: build dense Ahat[96x96] per graph ----------------
// Ahat[d][s] = sum over edges (s->d) of dis[s]*w*dis[d];  Ahat[i][i] += dis[i]^2
// Fully deterministic: per-dst-row serial accumulation.
__global__ __launch_bounds__(256) void prep_kernel(const void* __restrict__ ei_raw,
                                                   const float* __restrict__ attr)
{
    extern __shared__ char psm[];
    float*          A_s   = (float*)psm;                    // 90*96
    float*          w_s   = A_s + 90*96;                    // 1440
    float*          nrm_s = w_s + EPG;                      // 1440
    float*          dis_s = nrm_s + EPG;                    // 90
    int*            cnt_s = (int*)(dis_s + 90);             // 90
    int*            rp_s  = cnt_s + 90;                     // 91
    unsigned short* sd_s  = (unsigned short*)(rp_s + 91);   // 1440
    unsigned char*  src_s = (unsigned char*)(sd_s + EPG);   // 1440

    const int g = blockIdx.x, t = threadIdx.x;

    // dtype sniff: int64 edge_index has zero high words at odd int32 slots
    const int* e32 = (const int*)ei_raw;
    const long long* e64 = (const long long*)ei_raw;
    const bool is64 = ((e32[1] | e32[3] | e32[5] | e32[7] |
                        e32[9] | e32[11] | e32[13] | e32[15]) == 0);

    for (int i = t; i < NODES; i += 256) cnt_s[i] = 0;
    __syncthreads();

    const long long base = (long long)g * NODES;
    for (int e = t; e < EPG; e += 256) {
        const int gi = g*EPG + e;
        int s, d;
        if (is64) { s = (int)(e64[gi] - base); d = (int)(e64[E_TOT + gi] - base); }
        else      { s = e32[gi] - (int)base;   d = e32[E_TOT + gi] - (int)base;   }
        w_s[e]  = attr[gi];
        sd_s[e] = (unsigned short)(s | (d << 7));
        atomicAdd(&cnt_s[d], 1);                  // int atomic: deterministic
    }
    __syncthreads();

    if (t == 0) {
        int acc = 0;
        for (int i = 0; i < NODES; ++i) { rp_s[i] = acc; acc += cnt_s[i]; }
        rp_s[NODES] = acc;
    }
    __syncthreads();

    if (t < NODES) {                               // one thread owns one dst row
        const int i = t;
        int off = rp_s[i];
        float deg = 1.0f;                          // self-loop weight 1
        for (int e = 0; e < EPG; ++e) {
            const unsigned short sd = sd_s[e];
            if ((sd >> 7) == i) {
                const float w = w_s[e];
                deg += w;
                nrm_s[off] = w;                    // temp: raw weight
                src_s[off] = (unsigned char)(sd & 127);
                ++off;
            }
        }
        dis_s[i] = rsqrtf(deg);                    // deg >= 1 always
    }
    __syncthreads();

    for (int idx = t; idx < 90*96; idx += 256) A_s[idx] = 0.f;
    __syncthreads();

    if (t < NODES) {                               // dense row build (serial, dup-safe)
        const int i = t;
        const float di = dis_s[i];
        float* Arow = A_s + i*96;
        for (int p = rp_s[i]; p < rp_s[i+1]; ++p)
            Arow[src_s[p]] += dis_s[src_s[p]] * nrm_s[p] * di;
        Arow[i] += di * di;
    }
    __syncthreads();

    float4* out4 = (float4*)(g_adj + (size_t)g*96*96);
    const float4* A4 = (const float4*)A_s;
    for (int idx = t; idx < 96*24; idx += 256) {
        const int row = idx / 24;
        out4[idx] = (row < NODES) ? A4[idx] : make_float4(0.f, 0.f, 0.f, 0.f);
    }
}

// ---------------- fused GCNConv as two GEMMs, column-split (64 cols per CTA) --------
// Phase 1: h[96x64] = in[96xKPAD] @ W[KPAD x64]
// Phase 2: out[96x64] = Ahat[96x96] @ h[96x64] + bias, relu
// Ahat overlays the (dead) W+in smem region after phase 1.
template<int F, int KPAD>
__global__ __launch_bounds__(256, 2) void conv_kernel(
    const float* __restrict__ xin, int stride, int col_in,
    const float* __restrict__ W, const float* __restrict__ bias, int col_out)
{
    extern __shared__ float sm[];
    float* s_W  = sm;                       // KPAD*64
    float* s_in = s_W + KPAD*64;            // 96*KPAD
    float* s_h  = s_in + 96*KPAD;           // 96*64
    float* s_A  = sm;                       // overlay: 96*96 (fits in W+in region)

    const int g = blockIdx.x, t = threadIdx.x;
    const int h0 = blockIdx.y * 64;         // column half
    const int rg = t >> 4, cg = t & 15;     // 16 x 16 thread grid

    { // W[:, h0:h0+64] -> smem (float4); zero pad rows [F, KPAD)
        const float4* W4 = (const float4*)W;
        float4* sW4 = (float4*)s_W;
        for (int idx = t; idx < KPAD*16; idx += 256) {
            const int k = idx >> 4, c4 = idx & 15;
            sW4[idx] = (k < F) ? W4[k*32 + (h0 >> 2) + c4]
                               : make_float4(0.f, 0.f, 0.f, 0.f);
        }
    }
    if (F == 128) {                         // input from g_z, float4 path
        const float4* inb = (const float4*)(g_z + col_in);
        float4* si4 = (float4*)s_in;
        for (int idx = t; idx < 96*32; idx += 256) {
            const int i = idx >> 5, c4 = idx & 31;
            si4[i*(KPAD/4) + c4] = (i < NODES)
                ? inb[((size_t)(g*NODES + i)*stride >> 2) + c4]
                : make_float4(0.f, 0.f, 0.f, 0.f);
        }
    } else {                                // raw x, scalar, pad to KPAD
        for (int idx = t; idx < 96*KPAD; idx += 256) {
            const int i = idx / KPAD, k = idx - i*KPAD;
            s_in[idx] = (i < NODES && k < F)
                ? xin[(size_t)(g*NODES + i)*stride + k] : 0.f;
        }
    }
    __syncthreads();

    // -------- Phase 1 GEMM: h = in @ W, thread tile 6 rows x 4 cols --------
    {
        constexpr int K4 = KPAD / 4;
        float acc[6][4];
        #pragma unroll
        for (int r = 0; r < 6; ++r)
            acc[r][0]=acc[r][1]=acc[r][2]=acc[r][3]=0.f;

        const float4* in4 = (const float4*)s_in + rg*6*K4;
        const float4* W4s = (const float4*)s_W;
        #pragma unroll 2
        for (int k4 = 0; k4 < K4; ++k4) {
            float4 a[6];
            #pragma unroll
            for (int r = 0; r < 6; ++r) a[r] = in4[r*K4 + k4];
            #pragma unroll
            for (int j = 0; j < 4; ++j) {
                const float4 w = W4s[(k4*4 + j)*16 + cg];
                #pragma unroll
                for (int r = 0; r < 6; ++r) {
                    const float av = ((const float*)&a[r])[j];
                    acc[r][0] = fmaf(av, w.x, acc[r][0]);
                    acc[r][1] = fmaf(av, w.y, acc[r][1]);
                    acc[r][2] = fmaf(av, w.z, acc[r][2]);
                    acc[r][3] = fmaf(av, w.w, acc[r][3]);
                }
            }
        }
        float4* hout = (float4*)s_h + cg;
        #pragma unroll
        for (int r = 0; r < 6; ++r)
            hout[(rg*6 + r)*16] = make_float4(acc[r][0], acc[r][1], acc[r][2], acc[r][3]);
    }
    __syncthreads();

    // -------- load Ahat into overlay region --------
    {
        const float4* adj4 = (const float4*)(g_adj + (size_t)g*96*96);
        float4* sA4 = (float4*)s_A;
        for (int idx = t; idx < 96*24; idx += 256) sA4[idx] = adj4[idx];
    }
    __syncthreads();

    // -------- Phase 2 GEMM: out = Ahat @ h, + bias, relu, store --------
    {
        float acc[6][4];
        #pragma unroll
        for (int r = 0; r < 6; ++r)
            acc[r][0]=acc[r][1]=acc[r][2]=acc[r][3]=0.f;

        const float4* A4 = (const float4*)s_A + rg*6*24;
        const float4* h4 = (const float4*)s_h;
        #pragma unroll 2
        for (int k4 = 0; k4 < 24; ++k4) {
            float4 a[6];
            #pragma unroll
            for (int r = 0; r < 6; ++r) a[r] = A4[r*24 + k4];
            #pragma unroll
            for (int j = 0; j < 4; ++j) {
                const float4 w = h4[(k4*4 + j)*16 + cg];
                #pragma unroll
                for (int r = 0; r < 6; ++r) {
                    const float av = ((const float*)&a[r])[j];
                    acc[r][0] = fmaf(av, w.x, acc[r][0]);
                    acc[r][1] = fmaf(av, w.y, acc[r][1]);
                    acc[r][2] = fmaf(av, w.z, acc[r][2]);
                    acc[r][3] = fmaf(av, w.w, acc[r][3]);
                }
            }
        }
        const float4 bv = *(const float4*)(bias + h0 + cg*4);
        float* zbase = g_z + (size_t)g*ZW + col_out + h0;
        #pragma unroll
        for (int r = 0; r < 6; ++r) {
            const int row = rg*6 + r;
            if (row < NODES) {
                float4 o;
                o.x = fmaxf(acc[r][0] + bv.x, 0.f);
                o.y = fmaxf(acc[r][1] + bv.y, 0.f);
                o.z = fmaxf(acc[r][2] + bv.z, 0.f);
                o.w = fmaxf(acc[r][3] + bv.w, 0.f);
                *(float4*)(zbase + row*ZROW + cg*4) = o;
            }
        }
    }
}

// ---------------- lin1: [512 x 34560] @ [34560 x 64], 64x64 tiles, K-split x36 -----
__global__ __launch_bounds__(256) void lin1_kernel(const float* __restrict__ Wl)
{
    __shared__ float a_s[64*68];   // k-major, row stride 68 (transposed A tile)
    __shared__ float b_s[64*64];

    const int r0 = blockIdx.x * 64;
    const size_t k0 = (size_t)blockIdx.y * KCH;
    const int t = threadIdx.x;
    const int tr = t >> 4, tc = t & 15;

    float acc[4][4];
    #pragma unroll
    for (int u = 0; u < 4; ++u)
        acc[u][0]=acc[u][1]=acc[u][2]=acc[u][3]=0.f;

    for (int kt = 0; kt < KCH; kt += 64) {
        for (int q = t; q < 1024; q += 256) {          // a: 64 rows x 64 k (transposed)
            const int r = q >> 4, kq = (q & 15) * 4;
            const float4 v = *(const float4*)(g_z + (size_t)(r0 + r)*ZW + k0 + kt + kq);
            a_s[(kq+0)*68 + r] = v.x;
            a_s[(kq+1)*68 + r] = v.y;
            a_s[(kq+2)*68 + r] = v.z;
            a_s[(kq+3)*68 + r] = v.w;
        }
        for (int q = t; q < 1024; q += 256) {          // b: 64 k x 64 cols
            const int kk = q >> 4, cq = (q & 15) * 4;
            *(float4*)(b_s + kk*64 + cq) = *(const float4*)(Wl + (k0 + kt + kk)*64 + cq);
        }
        __syncthreads();
        #pragma unroll 8
        for (int kk = 0; kk < 64; ++kk) {
            const float4 av = *(const float4*)(a_s + kk*68 + tr*4);
            const float4 bb = *(const float4*)(b_s + kk*64 + tc*4);
            acc[0][0]=fmaf(av.x,bb.x,acc[0][0]); acc[0][1]=fmaf(av.x,bb.y,acc[0][1]);
            acc[0][2]=fmaf(av.x,bb.z,acc[0][2]); acc[0][3]=fmaf(av.x,bb.w,acc[0][3]);
            acc[1][0]=fmaf(av.y,bb.x,acc[1][0]); acc[1][1]=fmaf(av.y,bb.y,acc[1][1]);
            acc[1][2]=fmaf(av.y,bb.z,acc[1][2]); acc[1][3]=fmaf(av.y,bb.w,acc[1][3]);
            acc[2][0]=fmaf(av.z,bb.x,acc[2][0]); acc[2][1]=fmaf(av.z,bb.y,acc[2][1]);
            acc[2][2]=fmaf(av.z,bb.z,acc[2][2]); acc[2][3]=fmaf(av.z,bb.w,acc[2][3]);
            acc[3][0]=fmaf(av.w,bb.x,acc[3][0]); acc[3][1]=fmaf(av.w,bb.y,acc[3][1]);
            acc[3][2]=fmaf(av.w,bb.z,acc[3][2]); acc[3][3]=fmaf(av.w,bb.w,acc[3][3]);
        }
        __syncthreads();
    }
    float* pout = g_part + ((size_t)blockIdx.y*NB + r0) * HL;
    #pragma unroll
    for (int u = 0; u < 4; ++u)
        *(float4*)(pout + (tr*4+u)*HL + tc*4) =
            make_float4(acc[u][0], acc[u][1], acc[u][2], acc[u][3]);
}

__global__ __launch_bounds__(256) void lin1_reduce(const float* __restrict__ b)
{
    const int idx = blockIdx.x*256 + threadIdx.x;      // < 512*64
    float s = b[idx & 63];
    #pragma unroll
    for (int ks = 0; ks < KSPLIT; ++ks) s += g_part[(size_t)ks*NB*HL + idx];
    g_hid[idx] = fmaxf(s, 0.f);
}

// ---------------- head: hid @ lin2_W + b -> log_softmax ----------------
__global__ __launch_bounds__(64) void head_kernel(const float* __restrict__ W,
                                                  const float* __restrict__ bb,
                                                  float* __restrict__ out)
{
    const int g = blockIdx.x, t = threadIdx.x;
    const float v = g_hid[g*HL + t];
    float p0 = v * W[t*2 + 0];
    float p1 = v * W[t*2 + 1];
    #pragma unroll
    for (int o = 16; o; o >>= 1) {
        p0 += __shfl_down_sync(0xffffffffu, p0, o);
        p1 += __shfl_down_sync(0xffffffffu, p1, o);
    }
    __shared__ float s0[2], s1[2];
    if ((t & 31) == 0) { s0[t>>5] = p0; s1[t>>5] = p1; }
    __syncthreads();
    if (t == 0) {
        const float l0 = s0[0] + s0[1] + bb[0];
        const float l1 = s1[0] + s1[1] + bb[1];
        const float m = fmaxf(l0, l1);
        const float lse = m + logf(expf(l0 - m) + expf(l1 - m));
        out[g*2 + 0] = l0 - lse;
        out[g*2 + 1] = l1 - lse;
    }
}

// ---------------- launch ----------------
static const int SMEM90   = (92*64  + 96*92  + 96*64) * 4;   // 83456
static const int SMEM128  = (128*64 + 96*128 + 96*64) * 4;   // 106496
static const int PREPSMEM = (90*96 + EPG + EPG + 90) * 4 + (90+91)*4 + EPG*2 + EPG; // ~51.5KB

extern "C" void kernel_launch(void* const* d_in, const int* in_sizes, int n_in,
                              void* d_out, int out_size)
{
    const float* x        = (const float*)d_in[0];
    const float* eattr    = (const float*)d_in[1];
    const float* W1       = (const float*)d_in[2];
    const float* b1       = (const float*)d_in[3];
    const float* W2       = (const float*)d_in[4];
    const float* b2       = (const float*)d_in[5];
    const float* W3       = (const float*)d_in[6];
    const float* b3       = (const float*)d_in[7];
    const float* lin1_W   = (const float*)d_in[8];
    const float* lin1_b   = (const float*)d_in[9];
    const float* lin2_W   = (const float*)d_in[10];
    const float* lin2_b   = (const float*)d_in[11];
    const void*  eindex   = d_in[12];
    float* out = (float*)d_out;

    cudaFuncSetAttribute(prep_kernel,          cudaFuncAttributeMaxDynamicSharedMemorySize, PREPSMEM);
    cudaFuncSetAttribute(conv_kernel<90,92>,   cudaFuncAttributeMaxDynamicSharedMemorySize, SMEM90);
    cudaFuncSetAttribute(conv_kernel<128,128>, cudaFuncAttributeMaxDynamicSharedMemorySize, SMEM128);

    prep_kernel<<<NB, 256, PREPSMEM>>>(eindex, eattr);
    conv_kernel<90,92>  <<<dim3(NB,2), 256, SMEM90 >>>(x,       90,   0, W1, b1,   0);
    conv_kernel<128,128><<<dim3(NB,2), 256, SMEM128>>>(nullptr, ZROW, 0, W2, b2, 128);
    conv_kernel<128,128><<<dim3(NB,2), 256, SMEM128>>>(nullptr, ZROW, 128, W3, b3, 256);
    lin1_kernel<<<dim3(8, KSPLIT), 256>>>(lin1_W);
    lin1_reduce<<<NB*HL/256, 256>>>(lin1_b);
    head_kernel<<<NB, 64>>>(lin2_W, lin2_b, out);
}

// round 8
// speedup vs baseline: 1.1958x; 1.0783x over previous
#include <cuda_runtime.h>
#include <cuda_bf16.h>
#include <cstdint>
#include <math.h>

// ---------------- problem constants ----------------
#define NB     512            // graphs
#define NODES  90             // nodes per graph
#define NTOT   (NB*NODES)     // 46080
#define FIN    90
#define H      128
#define DEG    16
#define EPG    (NODES*DEG)    // 1440 edges per graph
#define E_TOT  (NTOT*DEG)     // 737280
#define ZROW   384            // 3*H, per-node width of concat buffer
#define ZW     (NODES*ZROW)   // 34560 per graph
#define HL     64
#define KSPLIT 36
#define KCH    960            // 34560/36

// ---------------- device scratch (static, no allocs) ----------------
__device__ float g_z[(size_t)NB*ZW];        // concat(h1,h2,h3) [g][node][l*128+f]
__device__ float g_adj[(size_t)NB*96*96];   // dense normalized adjacency, zero-padded
__device__ float g_part[(size_t)KSPLIT*NB*HL];
__device__ float g_hid[NB*HL];

// ---------------- warp-MMA helpers (sm_80+ ISA, compiles at plain sm_103) ---------
__device__ __forceinline__ uint32_t smem_u32(const void* p) {
    uint32_t a;
    asm("{ .reg .u64 tmp; cvta.to.shared.u64 tmp, %1; cvt.u32.u64 %0, tmp; }"
        : "=r"(a) : "l"(p));
    return a;
}
__device__ __forceinline__ void ldm_x4(uint32_t* r, uint32_t addr) {
    asm volatile("ldmatrix.sync.aligned.m8n8.x4.shared.b16 {%0,%1,%2,%3}, [%4];"
                 : "=r"(r[0]), "=r"(r[1]), "=r"(r[2]), "=r"(r[3]) : "r"(addr));
}
__device__ __forceinline__ void ldm_x2(uint32_t* r, uint32_t addr) {
    asm volatile("ldmatrix.sync.aligned.m8n8.x2.shared.b16 {%0,%1}, [%2];"
                 : "=r"(r[0]), "=r"(r[1]) : "r"(addr));
}
__device__ __forceinline__ void mma_bf16(float* d, const uint32_t* a, const uint32_t* b) {
    asm volatile("mma.sync.aligned.m16n8k16.row.col.f32.bf16.bf16.f32 "
                 "{%0,%1,%2,%3}, {%4,%5,%6,%7}, {%8,%9}, {%0,%1,%2,%3};"
                 : "+f"(d[0]), "+f"(d[1]), "+f"(d[2]), "+f"(d[3])
                 : "r"(a[0]), "r"(a[1]), "r"(a[2]), "r"(a[3]), "r"(b[0]), "r"(b[1]));
}
// bf16 hi/lo split helpers
__device__ __forceinline__ unsigned short bf_hi(float a, float& rem) {
    const __nv_bfloat16 h = __float2bfloat16_rn(a);
    rem = a - __bfloat162float(h);
    return __bfloat16_as_ushort(h);
}
__device__ __forceinline__ unsigned short bf_rn(float a) {
    return __bfloat16_as_ushort(__float2bfloat16_rn(a));
}

// ---------------- prep: build dense Ahat[96x96] per graph ----------------
__global__ __launch_bounds__(256) void prep_kernel(const void* __restrict__ ei_raw,
                                                   const float* __restrict__ attr)
{
    extern __shared__ char psm[];
    float*          A_s   = (float*)psm;                    // 90*96
    float*          w_s   = A_s + 90*96;                    // 1440
    float*          nrm_s = w_s + EPG;                      // 1440
    float*          dis_s = nrm_s + EPG;                    // 90
    int*            cnt_s = (int*)(dis_s + 90);             // 90
    int*            rp_s  = cnt_s + 90;                     // 91
    unsigned short* sd_s  = (unsigned short*)(rp_s + 91);   // 1440
    unsigned char*  src_s = (unsigned char*)(sd_s + EPG);   // 1440

    const int g = blockIdx.x, t = threadIdx.x;

    const int* e32 = (const int*)ei_raw;
    const long long* e64 = (const long long*)ei_raw;
    const bool is64 = ((e32[1] | e32[3] | e32[5] | e32[7] |
                        e32[9] | e32[11] | e32[13] | e32[15]) == 0);

    for (int i = t; i < NODES; i += 256) cnt_s[i] = 0;
    __syncthreads();

    const long long base = (long long)g * NODES;
    for (int e = t; e < EPG; e += 256) {
        const int gi = g*EPG + e;
        int s, d;
        if (is64) { s = (int)(e64[gi] - base); d = (int)(e64[E_TOT + gi] - base); }
        else      { s = e32[gi] - (int)base;   d = e32[E_TOT + gi] - (int)base;   }
        w_s[e]  = attr[gi];
        sd_s[e] = (unsigned short)(s | (d << 7));
        atomicAdd(&cnt_s[d], 1);
    }
    __syncthreads();

    if (t == 0) {
        int acc = 0;
        for (int i = 0; i < NODES; ++i) { rp_s[i] = acc; acc += cnt_s[i]; }
        rp_s[NODES] = acc;
    }
    __syncthreads();

    if (t < NODES) {
        const int i = t;
        int off = rp_s[i];
        float deg = 1.0f;
        for (int e = 0; e < EPG; ++e) {
            const unsigned short sd = sd_s[e];
            if ((sd >> 7) == i) {
                const float w = w_s[e];
                deg += w;
                nrm_s[off] = w;
                src_s[off] = (unsigned char)(sd & 127);
                ++off;
            }
        }
        dis_s[i] = rsqrtf(deg);
    }
    __syncthreads();

    for (int idx = t; idx < 90*96; idx += 256) A_s[idx] = 0.f;
    __syncthreads();

    if (t < NODES) {
        const int i = t;
        const float di = dis_s[i];
        float* Arow = A_s + i*96;
        for (int p = rp_s[i]; p < rp_s[i+1]; ++p)
            Arow[src_s[p]] += dis_s[src_s[p]] * nrm_s[p] * di;
        Arow[i] += di * di;
    }
    __syncthreads();

    float4* out4 = (float4*)(g_adj + (size_t)g*96*96);
    const float4* A4 = (const float4*)A_s;
    for (int idx = t; idx < 96*24; idx += 256) {
        const int row = idx / 24;
        out4[idx] = (row < NODES) ? A4[idx] : make_float4(0.f, 0.f, 0.f, 0.f);
    }
}

// ---------------- fused GCNConv as two GEMMs, column-split (unchanged) --------
template<int F, int KPAD>
__global__ __launch_bounds__(256, 2) void conv_kernel(
    const float* __restrict__ xin, int stride, int col_in,
    const float* __restrict__ W, const float* __restrict__ bias, int col_out)
{
    extern __shared__ float sm[];
    float* s_W  = sm;
    float* s_in = s_W + KPAD*64;
    float* s_h  = s_in + 96*KPAD;
    float* s_A  = sm;                       // overlay

    const int g = blockIdx.x, t = threadIdx.x;
    const int h0 = blockIdx.y * 64;
    const int rg = t >> 4, cg = t & 15;

    {
        const float4* W4 = (const float4*)W;
        float4* sW4 = (float4*)s_W;
        for (int idx = t; idx < KPAD*16; idx += 256) {
            const int k = idx >> 4, c4 = idx & 15;
            sW4[idx] = (k < F) ? W4[k*32 + (h0 >> 2) + c4]
                               : make_float4(0.f, 0.f, 0.f, 0.f);
        }
    }
    if (F == 128) {
        const float4* inb = (const float4*)(g_z + col_in);
        float4* si4 = (float4*)s_in;
        for (int idx = t; idx < 96*32; idx += 256) {
            const int i = idx >> 5, c4 = idx & 31;
            si4[i*(KPAD/4) + c4] = (i < NODES)
                ? inb[((size_t)(g*NODES + i)*stride >> 2) + c4]
                : make_float4(0.f, 0.f, 0.f, 0.f);
        }
    } else {
        for (int idx = t; idx < 96*KPAD; idx += 256) {
            const int i = idx / KPAD, k = idx - i*KPAD;
            s_in[idx] = (i < NODES && k < F)
                ? xin[(size_t)(g*NODES + i)*stride + k] : 0.f;
        }
    }
    __syncthreads();

    {
        constexpr int K4 = KPAD / 4;
        float acc[6][4];
        #pragma unroll
        for (int r = 0; r < 6; ++r)
            acc[r][0]=acc[r][1]=acc[r][2]=acc[r][3]=0.f;

        const float4* in4 = (const float4*)s_in + rg*6*K4;
        const float4* W4s = (const float4*)s_W;
        #pragma unroll 2
        for (int k4 = 0; k4 < K4; ++k4) {
            float4 a[6];
            #pragma unroll
            for (int r = 0; r < 6; ++r) a[r] = in4[r*K4 + k4];
            #pragma unroll
            for (int j = 0; j < 4; ++j) {
                const float4 w = W4s[(k4*4 + j)*16 + cg];
                #pragma unroll
                for (int r = 0; r < 6; ++r) {
                    const float av = ((const float*)&a[r])[j];
                    acc[r][0] = fmaf(av, w.x, acc[r][0]);
                    acc[r][1] = fmaf(av, w.y, acc[r][1]);
                    acc[r][2] = fmaf(av, w.z, acc[r][2]);
                    acc[r][3] = fmaf(av, w.w, acc[r][3]);
                }
            }
        }
        float4* hout = (float4*)s_h + cg;
        #pragma unroll
        for (int r = 0; r < 6; ++r)
            hout[(rg*6 + r)*16] = make_float4(acc[r][0], acc[r][1], acc[r][2], acc[r][3]);
    }
    __syncthreads();

    {
        const float4* adj4 = (const float4*)(g_adj + (size_t)g*96*96);
        float4* sA4 = (float4*)s_A;
        for (int idx = t; idx < 96*24; idx += 256) sA4[idx] = adj4[idx];
    }
    __syncthreads();

    {
        float acc[6][4];
        #pragma unroll
        for (int r = 0; r < 6; ++r)
            acc[r][0]=acc[r][1]=acc[r][2]=acc[r][3]=0.f;

        const float4* A4 = (const float4*)s_A + rg*6*24;
        const float4* h4 = (const float4*)s_h;
        #pragma unroll 2
        for (int k4 = 0; k4 < 24; ++k4) {
            float4 a[6];
            #pragma unroll
            for (int r = 0; r < 6; ++r) a[r] = A4[r*24 + k4];
            #pragma unroll
            for (int j = 0; j < 4; ++j) {
                const float4 w = h4[(k4*4 + j)*16 + cg];
                #pragma unroll
                for (int r = 0; r < 6; ++r) {
                    const float av = ((const float*)&a[r])[j];
                    acc[r][0] = fmaf(av, w.x, acc[r][0]);
                    acc[r][1] = fmaf(av, w.y, acc[r][1]);
                    acc[r][2] = fmaf(av, w.z, acc[r][2]);
                    acc[r][3] = fmaf(av, w.w, acc[r][3]);
                }
            }
        }
        const float4 bv = *(const float4*)(bias + h0 + cg*4);
        float* zbase = g_z + (size_t)g*ZW + col_out + h0;
        #pragma unroll
        for (int r = 0; r < 6; ++r) {
            const int row = rg*6 + r;
            if (row < NODES) {
                float4 o;
                o.x = fmaxf(acc[r][0] + bv.x, 0.f);
                o.y = fmaxf(acc[r][1] + bv.y, 0.f);
                o.z = fmaxf(acc[r][2] + bv.z, 0.f);
                o.w = fmaxf(acc[r][3] + bv.w, 0.f);
                *(float4*)(zbase + row*ZROW + cg*4) = o;
            }
        }
    }
}

// ---------------- lin1 via warp-MMA: bf16 3-term emulated fp32 GEMM ----------------
// CTA = 128 threads (4 warps), M-tile 64, N=64, K-chunk KCH in 64-tiles.
// Warp w owns rows [w*16, w*16+16). acc[n][4] in fp32 registers.
// smem tiles stride 72 b16 (144B rows -> conflict-free ldmatrix).
__global__ __launch_bounds__(128) void lin1_mma(const float* __restrict__ Wl)
{
    __shared__ __align__(16) unsigned short Ahi[64*72];
    __shared__ __align__(16) unsigned short Alo[64*72];
    __shared__ __align__(16) unsigned short Bhi[64*72];
    __shared__ __align__(16) unsigned short Blo[64*72];

    const int t = threadIdx.x, lane = t & 31, w = t >> 5;
    const int r0 = blockIdx.x * 64;
    const size_t kbase = (size_t)blockIdx.y * KCH;

    float acc[8][4];
    #pragma unroll
    for (int n = 0; n < 8; ++n)
        acc[n][0]=acc[n][1]=acc[n][2]=acc[n][3]=0.f;

    // ldmatrix source addresses (element offsets computed per k-step below)
    const uint32_t aRowA = (uint32_t)((w*16 + (lane & 15))*72 + ((lane >> 4) << 3));
    const uint32_t aRowB = (uint32_t)(((lane & 7))*72 + (((lane >> 3) & 1) << 3));
    const uint32_t sAhi = smem_u32(Ahi), sAlo = smem_u32(Alo);
    const uint32_t sBhi = smem_u32(Bhi), sBlo = smem_u32(Blo);

    for (int kt = 0; kt < KCH; kt += 64) {
        // ---- A tile: 64 rows x 64 k, convert to hi/lo bf16 ----
        #pragma unroll
        for (int i = 0; i < 8; ++i) {
            const int idx = i*128 + t;            // 1024 float4
            const int row = idx >> 4, k4 = idx & 15;
            const float4 v = *(const float4*)(g_z + (size_t)(r0 + row)*ZW + kbase + kt + k4*4);
            float rx, ry, rz, rw;
            const ushort4 hi = make_ushort4(bf_hi(v.x, rx), bf_hi(v.y, ry),
                                            bf_hi(v.z, rz), bf_hi(v.w, rw));
            const ushort4 lo = make_ushort4(bf_rn(rx), bf_rn(ry), bf_rn(rz), bf_rn(rw));
            *(ushort4*)(Ahi + row*72 + k4*4) = hi;
            *(ushort4*)(Alo + row*72 + k4*4) = lo;
        }
        // ---- B tile: 64 k x 64 n, store transposed Bt[n][k] ----
        #pragma unroll
        for (int i = 0; i < 8; ++i) {
            const int idx = i*128 + t;
            const int kk = idx >> 4, n4 = idx & 15;
            const float4 v = *(const float4*)(Wl + (kbase + kt + kk)*64 + n4*4);
            const float vv[4] = {v.x, v.y, v.z, v.w};
            #pragma unroll
            for (int j = 0; j < 4; ++j) {
                float r;
                const unsigned short h = bf_hi(vv[j], r);
                Bhi[(n4*4 + j)*72 + kk] = h;
                Blo[(n4*4 + j)*72 + kk] = bf_rn(r);
            }
        }
        __syncthreads();

        // ---- 4 k-steps of m16n8k16, 3 terms each ----
        #pragma unroll
        for (int ks = 0; ks < 4; ++ks) {
            uint32_t ah[4], al[4];
            ldm_x4(ah, sAhi + 2*(aRowA + ks*16));
            ldm_x4(al, sAlo + 2*(aRowA + ks*16));
            #pragma unroll
            for (int n = 0; n < 8; ++n) {
                uint32_t bh[2], bl[2];
                ldm_x2(bh, sBhi + 2*(aRowB + (uint32_t)(n*8*72) + ks*16));
                ldm_x2(bl, sBlo + 2*(aRowB + (uint32_t)(n*8*72) + ks*16));
                mma_bf16(acc[n], ah, bh);
                mma_bf16(acc[n], ah, bl);
                mma_bf16(acc[n], al, bh);
            }
        }
        __syncthreads();
    }

    // ---- store partials: D frag mapping (m16n8): rows lane/4, lane/4+8; cols (lane%3)*2 ----
    const int row = lane >> 2, colp = (lane & 3)*2;
    const int m = r0 + w*16;
    float* pout = g_part + (size_t)blockIdx.y*NB*HL;
    #pragma unroll
    for (int n = 0; n < 8; ++n) {
        *(float2*)(pout + (size_t)(m + row    )*HL + n*8 + colp) = make_float2(acc[n][0], acc[n][1]);
        *(float2*)(pout + (size_t)(m + row + 8)*HL + n*8 + colp) = make_float2(acc[n][2], acc[n][3]);
    }
}

__global__ __launch_bounds__(256) void lin1_reduce(const float* __restrict__ b)
{
    const int idx = blockIdx.x*256 + threadIdx.x;      // < 512*64
    float s = b[idx & 63];
    #pragma unroll
    for (int ks = 0; ks < KSPLIT; ++ks) s += g_part[(size_t)ks*NB*HL + idx];
    g_hid[idx] = fmaxf(s, 0.f);
}

// ---------------- head: hid @ lin2_W + b -> log_softmax ----------------
__global__ __launch_bounds__(64) void head_kernel(const float* __restrict__ W,
                                                  const float* __restrict__ bb,
                                                  float* __restrict__ out)
{
    const int g = blockIdx.x, t = threadIdx.x;
    const float v = g_hid[g*HL + t];
    float p0 = v * W[t*2 + 0];
    float p1 = v * W[t*2 + 1];
    #pragma unroll
    for (int o = 16; o; o >>= 1) {
        p0 += __shfl_down_sync(0xffffffffu, p0, o);
        p1 += __shfl_down_sync(0xffffffffu, p1, o);
    }
    __shared__ float s0[2], s1[2];
    if ((t & 31) == 0) { s0[t>>5] = p0; s1[t>>5] = p1; }
    __syncthreads();
    if (t == 0) {
        const float l0 = s0[0] + s0[1] + bb[0];
        const float l1 = s1[0] + s1[1] + bb[1];
        const float m = fmaxf(l0, l1);
        const float lse = m + logf(expf(l0 - m) + expf(l1 - m));
        out[g*2 + 0] = l0 - lse;
        out[g*2 + 1] = l1 - lse;
    }
}

// ---------------- launch ----------------
static const int SMEM90   = (92*64  + 96*92  + 96*64) * 4;   // 83456
static const int SMEM128  = (128*64 + 96*128 + 96*64) * 4;   // 106496
static const int PREPSMEM = (90*96 + EPG + EPG + 90) * 4 + (90+91)*4 + EPG*2 + EPG;

extern "C" void kernel_launch(void* const* d_in, const int* in_sizes, int n_in,
                              void* d_out, int out_size)
{
    const float* x        = (const float*)d_in[0];
    const float* eattr    = (const float*)d_in[1];
    const float* W1       = (const float*)d_in[2];
    const float* b1       = (const float*)d_in[3];
    const float* W2       = (const float*)d_in[4];
    const float* b2       = (const float*)d_in[5];
    const float* W3       = (const float*)d_in[6];
    const float* b3       = (const float*)d_in[7];
    const float* lin1_W   = (const float*)d_in[8];
    const float* lin1_b   = (const float*)d_in[9];
    const float* lin2_W   = (const float*)d_in[10];
    const float* lin2_b   = (const float*)d_in[11];
    const void*  eindex   = d_in[12];
    float* out = (float*)d_out;

    cudaFuncSetAttribute(prep_kernel,          cudaFuncAttributeMaxDynamicSharedMemorySize, PREPSMEM);
    cudaFuncSetAttribute(conv_kernel<90,92>,   cudaFuncAttributeMaxDynamicSharedMemorySize, SMEM90);
    cudaFuncSetAttribute(conv_kernel<128,128>, cudaFuncAttributeMaxDynamicSharedMemorySize, SMEM128);

    prep_kernel<<<NB, 256, PREPSMEM>>>(eindex, eattr);
    conv_kernel<90,92>  <<<dim3(NB,2), 256, SMEM90 >>>(x,       90,   0, W1, b1,   0);
    conv_kernel<128,128><<<dim3(NB,2), 256, SMEM128>>>(nullptr, ZROW, 0, W2, b2, 128);
    conv_kernel<128,128><<<dim3(NB,2), 256, SMEM128>>>(nullptr, ZROW, 128, W3, b3, 256);
    lin1_mma<<<dim3(8, KSPLIT), 128>>>(lin1_W);
    lin1_reduce<<<NB*HL/256, 256>>>(lin1_b);
    head_kernel<<<NB, 64>>>(lin2_W, lin2_b, out);
}

// round 16
// speedup vs baseline: 1.3499x; 1.1290x over previous
#include <cuda_runtime.h>
#include <cuda_bf16.h>
#include <cstdint>
#include <math.h>

// ---------------- problem constants ----------------
#define NB     512
#define NODES  90
#define NTOT   (NB*NODES)
#define FIN    90
#define H      128
#define DEG    16
#define EPG    (NODES*DEG)    // 1440
#define E_TOT  (NTOT*DEG)     // 737280
#define ZROW   384            // 3*H
#define ZW     (NODES*ZROW)   // 34560
#define HL     64
#define KSPLIT 36
#define KCH    960            // 34560/36

typedef unsigned short ushort_t;

// ---------------- device scratch (static, no allocs) ----------------
__device__ float g_z[(size_t)NB*ZW];        // fp32 concat(h1,h2,h3) (round 3-8 proven)
__device__ float g_adj[(size_t)NB*96*96];   // fp32 dense Ahat (round 3-8 proven)
__device__ float g_part[(size_t)KSPLIT*NB*HL];
__device__ float g_hid[NB*HL];

// ---------------- helpers (all round-8 proven) ----------------
__device__ __forceinline__ uint32_t smem_u32(const void* p) {
    uint32_t a;
    asm("{ .reg .u64 tmp; cvta.to.shared.u64 tmp, %1; cvt.u32.u64 %0, tmp; }"
        : "=r"(a) : "l"(p));
    return a;
}
__device__ __forceinline__ void ldm_x4(uint32_t* r, uint32_t addr) {
    asm volatile("ldmatrix.sync.aligned.m8n8.x4.shared.b16 {%0,%1,%2,%3}, [%4];"
                 : "=r"(r[0]), "=r"(r[1]), "=r"(r[2]), "=r"(r[3]) : "r"(addr));
}
__device__ __forceinline__ void ldm_x2(uint32_t* r, uint32_t addr) {
    asm volatile("ldmatrix.sync.aligned.m8n8.x2.shared.b16 {%0,%1}, [%2];"
                 : "=r"(r[0]), "=r"(r[1]) : "r"(addr));
}
__device__ __forceinline__ void mma_bf16(float* d, const uint32_t* a, const uint32_t* b) {
    asm volatile("mma.sync.aligned.m16n8k16.row.col.f32.bf16.bf16.f32 "
                 "{%0,%1,%2,%3}, {%4,%5,%6,%7}, {%8,%9}, {%0,%1,%2,%3};"
                 : "+f"(d[0]), "+f"(d[1]), "+f"(d[2]), "+f"(d[3])
                 : "r"(a[0]), "r"(a[1]), "r"(a[2]), "r"(a[3]), "r"(b[0]), "r"(b[1]));
}
__device__ __forceinline__ ushort_t bf_hi(float a, float& rem) {
    const __nv_bfloat16 h = __float2bfloat16_rn(a);
    rem = a - __bfloat162float(h);
    return __bfloat16_as_ushort(h);
}
__device__ __forceinline__ ushort_t bf_rn(float a) {
    return __bfloat16_as_ushort(__float2bfloat16_rn(a));
}

// ---------------- prep: dense fp32 Ahat[96x96] per graph (round-3 proven) ----------------
__global__ __launch_bounds__(256) void prep_kernel(const void* __restrict__ ei_raw,
                                                   const float* __restrict__ attr)
{
    extern __shared__ char psm[];
    float*          A_s   = (float*)psm;                    // 90*96
    float*          w_s   = A_s + 90*96;                    // 1440
    float*          nrm_s = w_s + EPG;                      // 1440
    float*          dis_s = nrm_s + EPG;                    // 90
    int*            cnt_s = (int*)(dis_s + 90);             // 90
    int*            rp_s  = cnt_s + 90;                     // 91
    unsigned short* sd_s  = (unsigned short*)(rp_s + 91);   // 1440
    unsigned char*  src_s = (unsigned char*)(sd_s + EPG);   // 1440

    const int g = blockIdx.x, t = threadIdx.x;

    const int* e32 = (const int*)ei_raw;
    const long long* e64 = (const long long*)ei_raw;
    const bool is64 = ((e32[1] | e32[3] | e32[5] | e32[7] |
                        e32[9] | e32[11] | e32[13] | e32[15]) == 0);

    for (int i = t; i < NODES; i += 256) cnt_s[i] = 0;
    __syncthreads();

    const long long base = (long long)g * NODES;
    for (int e = t; e < EPG; e += 256) {
        const int gi = g*EPG + e;
        int s, d;
        if (is64) { s = (int)(e64[gi] - base); d = (int)(e64[E_TOT + gi] - base); }
        else      { s = e32[gi] - (int)base;   d = e32[E_TOT + gi] - (int)base;   }
        w_s[e]  = attr[gi];
        sd_s[e] = (unsigned short)(s | (d << 7));
        atomicAdd(&cnt_s[d], 1);
    }
    __syncthreads();

    if (t == 0) {
        int acc = 0;
        for (int i = 0; i < NODES; ++i) { rp_s[i] = acc; acc += cnt_s[i]; }
        rp_s[NODES] = acc;
    }
    __syncthreads();

    if (t < NODES) {
        const int i = t;
        int off = rp_s[i];
        float deg = 1.0f;
        for (int e = 0; e < EPG; ++e) {
            const unsigned short sd = sd_s[e];
            if ((sd >> 7) == i) {
                const float w = w_s[e];
                deg += w;
                nrm_s[off] = w;
                src_s[off] = (unsigned char)(sd & 127);
                ++off;
            }
        }
        dis_s[i] = rsqrtf(deg);
    }
    __syncthreads();

    for (int idx = t; idx < 90*96; idx += 256) A_s[idx] = 0.f;
    __syncthreads();

    if (t < NODES) {
        const int i = t;
        const float di = dis_s[i];
        float* Arow = A_s + i*96;
        for (int p = rp_s[i]; p < rp_s[i+1]; ++p)
            Arow[src_s[p]] += dis_s[src_s[p]] * nrm_s[p] * di;
        Arow[i] += di * di;
    }
    __syncthreads();

    float4* out4 = (float4*)(g_adj + (size_t)g*9216);
    const float4* A4 = (const float4*)A_s;
    for (int idx = t; idx < 96*24; idx += 256) {
        const int row = idx / 24;
        out4[idx] = (row < NODES) ? A4[idx] : make_float4(0.f, 0.f, 0.f, 0.f);
    }
}

// ---------------- conv via warp-MMA, built strictly from round-8-proven pieces -------
template<int K, int KH>
__global__ __launch_bounds__(256, 2) void conv_mma(
    const float* __restrict__ in, int gstride, int rstride, int ksrc, int col_in,
    const float* __restrict__ W, const float* __restrict__ bias, int col_out)
{
    constexpr int KS    = KH + 8;
    constexpr int A_H   = 0;
    constexpr int A_L   = 96*KS;
    constexpr int BW_H  = 2*96*KS;
    constexpr int BW_L  = BW_H + 64*KS;
    constexpr int P1END = BW_H + 2*64*KS;      // ushort offsets
    constexpr int HF    = P1END;                // fp32 h region (12288 ushorts)
    constexpr int BT_H  = P1END + 12288;
    constexpr int BT_L  = BT_H + 64*104;
    constexpr int ADJ_H = 0;                    // overlays phase-1 (dead) region
    constexpr int ADJ_L = 96*104;

    extern __shared__ ushort_t csm[];
    float* hS = (float*)(csm + HF);
    const uint32_t sb = smem_u32(csm);

    const int g = blockIdx.x, t = threadIdx.x;
    const int h0 = blockIdx.y * 64;
    const int lane = t & 31, w = t >> 5;
    const int mw = w >> 2, nw = w & 3;
    const uint32_t lrow  = lane & 15, lcol  = (lane >> 4) << 3;
    const uint32_t lrow8 = lane & 7,  lcol8 = ((lane >> 3) & 1) << 3;

    const float* inb = in + (size_t)g*gstride + col_in;

    float acc[3][2][4];
    #pragma unroll
    for (int a = 0; a < 3; ++a)
        #pragma unroll
        for (int b = 0; b < 2; ++b)
            acc[a][b][0]=acc[a][b][1]=acc[a][b][2]=acc[a][b][3]=0.f;

    // ---------------- phase 1 over K halves ----------------
    #pragma unroll
    for (int kh = 0; kh < K; kh += KH) {
        for (int idx = t; idx < 96*KH; idx += 256) {      // A tile hi/lo
            const int row = idx / KH, k = idx - row*KH;
            const int kg = kh + k;
            const float v = (row < NODES && kg < ksrc)
                ? inb[(size_t)row*rstride + kg] : 0.f;
            float r;
            csm[A_H + row*KS + k] = bf_hi(v, r);
            csm[A_L + row*KS + k] = bf_rn(r);
        }
        for (int idx = t; idx < 64*KH; idx += 256) {      // W -> Bt[n][k]
            const int n = idx & 63, k = idx >> 6;
            const int kg = kh + k;
            const float v = (kg < ksrc) ? W[(size_t)kg*128 + h0 + n] : 0.f;
            float r;
            csm[BW_H + n*KS + k] = bf_hi(v, r);
            csm[BW_L + n*KS + k] = bf_rn(r);
        }
        __syncthreads();

        #pragma unroll
        for (int ks = 0; ks < KH/16; ++ks) {
            uint32_t ah[3][4], al[3][4];
            #pragma unroll
            for (int ti = 0; ti < 3; ++ti) {
                const uint32_t ao = (uint32_t)((mw*48 + ti*16 + lrow)*KS + ks*16) + lcol;
                ldm_x4(ah[ti], sb + 2*(A_H + ao));
                ldm_x4(al[ti], sb + 2*(A_L + ao));
            }
            #pragma unroll
            for (int nb = 0; nb < 2; ++nb) {
                uint32_t bh[2], bl[2];
                const uint32_t bo = (uint32_t)((nw*16 + nb*8 + lrow8)*KS + ks*16) + lcol8;
                ldm_x2(bh, sb + 2*(BW_H + bo));
                ldm_x2(bl, sb + 2*(BW_L + bo));
                #pragma unroll
                for (int ti = 0; ti < 3; ++ti) {
                    mma_bf16(acc[ti][nb], ah[ti], bh);
                    mma_bf16(acc[ti][nb], ah[ti], bl);
                    mma_bf16(acc[ti][nb], al[ti], bh);
                }
            }
        }
        __syncthreads();
    }

    // ---------------- store h fp32 (proven D-fragment float2 store) ----------------
    {
        const int rowD = lane >> 2, colD = (lane & 3)*2;
        #pragma unroll
        for (int ti = 0; ti < 3; ++ti)
            #pragma unroll
            for (int nb = 0; nb < 2; ++nb) {
                const int m0 = mw*48 + ti*16 + rowD;
                const int n0 = nw*16 + nb*8 + colD;
                *(float2*)(hS + m0*64 + n0)       = make_float2(acc[ti][nb][0], acc[ti][nb][1]);
                *(float2*)(hS + (m0 + 8)*64 + n0) = make_float2(acc[ti][nb][2], acc[ti][nb][3]);
            }
    }
    __syncthreads();

    // ---------------- h -> Bt2 [n=64][k=96] hi/lo ----------------
    for (int idx = t; idx < 64*96; idx += 256) {
        const int n = idx & 63, m = idx >> 6;
        const float v = hS[m*64 + n];
        float r;
        csm[BT_H + n*104 + m] = bf_hi(v, r);
        csm[BT_L + n*104 + m] = bf_rn(r);
    }
    __syncthreads();

    // ---------------- adj fp32 -> hi/lo [m=96][k=96] ----------------
    for (int idx = t; idx < 96*96; idx += 256) {
        const int m = idx / 96, k = idx - m*96;
        const float v = g_adj[(size_t)g*9216 + idx];
        float r;
        csm[ADJ_H + m*104 + k] = bf_hi(v, r);
        csm[ADJ_L + m*104 + k] = bf_rn(r);
    }
    __syncthreads();

    // ---------------- phase 2: out = Ahat @ h ----------------
    #pragma unroll
    for (int a = 0; a < 3; ++a)
        #pragma unroll
        for (int b = 0; b < 2; ++b)
            acc[a][b][0]=acc[a][b][1]=acc[a][b][2]=acc[a][b][3]=0.f;

    #pragma unroll
    for (int ks = 0; ks < 6; ++ks) {
        uint32_t ah[3][4], al[3][4];
        #pragma unroll
        for (int ti = 0; ti < 3; ++ti) {
            const uint32_t ao = (uint32_t)((mw*48 + ti*16 + lrow)*104 + ks*16) + lcol;
            ldm_x4(ah[ti], sb + 2*(ADJ_H + ao));
            ldm_x4(al[ti], sb + 2*(ADJ_L + ao));
        }
        #pragma unroll
        for (int nb = 0; nb < 2; ++nb) {
            uint32_t bh[2], bl[2];
            const uint32_t bo = (uint32_t)((nw*16 + nb*8 + lrow8)*104 + ks*16) + lcol8;
            ldm_x2(bh, sb + 2*(BT_H + bo));
            ldm_x2(bl, sb + 2*(BT_L + bo));
            #pragma unroll
            for (int ti = 0; ti < 3; ++ti) {
                mma_bf16(acc[ti][nb], ah[ti], bh);
                mma_bf16(acc[ti][nb], ah[ti], bl);
                mma_bf16(acc[ti][nb], al[ti], bh);
            }
        }
    }

    // ---------------- epilogue: +bias, relu, store fp32 g_z ----------------
    {
        const int rowD = lane >> 2, colD = (lane & 3)*2;
        #pragma unroll
        for (int ti = 0; ti < 3; ++ti)
            #pragma unroll
            for (int nb = 0; nb < 2; ++nb) {
                const int m0 = mw*48 + ti*16 + rowD;
                const int n0 = nw*16 + nb*8 + colD;
                const float2 bv = *(const float2*)(bias + h0 + n0);
                float* zb = g_z + (size_t)g*ZW + col_out + h0 + n0;
                if (m0 < NODES)
                    *(float2*)(zb + (size_t)m0*ZROW) = make_float2(
                        fmaxf(acc[ti][nb][0] + bv.x, 0.f),
                        fmaxf(acc[ti][nb][1] + bv.y, 0.f));
                if (m0 + 8 < NODES)
                    *(float2*)(zb + (size_t)(m0 + 8)*ZROW) = make_float2(
                        fmaxf(acc[ti][nb][2] + bv.x, 0.f),
                        fmaxf(acc[ti][nb][3] + bv.y, 0.f));
            }
    }
}

// ---------------- lin1 via warp-MMA: VERBATIM round-8 passing kernel ----------------
__global__ __launch_bounds__(128) void lin1_mma(const float* __restrict__ Wl)
{
    __shared__ __align__(16) unsigned short Ahi[64*72];
    __shared__ __align__(16) unsigned short Alo[64*72];
    __shared__ __align__(16) unsigned short Bhi[64*72];
    __shared__ __align__(16) unsigned short Blo[64*72];

    const int t = threadIdx.x, lane = t & 31, w = t >> 5;
    const int r0 = blockIdx.x * 64;
    const size_t kbase = (size_t)blockIdx.y * KCH;

    float acc[8][4];
    #pragma unroll
    for (int n = 0; n < 8; ++n)
        acc[n][0]=acc[n][1]=acc[n][2]=acc[n][3]=0.f;

    const uint32_t aRowA = (uint32_t)((w*16 + (lane & 15))*72 + ((lane >> 4) << 3));
    const uint32_t aRowB = (uint32_t)(((lane & 7))*72 + (((lane >> 3) & 1) << 3));
    const uint32_t sAhi = smem_u32(Ahi), sAlo = smem_u32(Alo);
    const uint32_t sBhi = smem_u32(Bhi), sBlo = smem_u32(Blo);

    for (int kt = 0; kt < KCH; kt += 64) {
        #pragma unroll
        for (int i = 0; i < 8; ++i) {
            const int idx = i*128 + t;
            const int row = idx >> 4, k4 = idx & 15;
            const float4 v = *(const float4*)(g_z + (size_t)(r0 + row)*ZW + kbase + kt + k4*4);
            float rx, ry, rz, rw;
            const ushort4 hi = make_ushort4(bf_hi(v.x, rx), bf_hi(v.y, ry),
                                            bf_hi(v.z, rz), bf_hi(v.w, rw));
            const ushort4 lo = make_ushort4(bf_rn(rx), bf_rn(ry), bf_rn(rz), bf_rn(rw));
            *(ushort4*)(Ahi + row*72 + k4*4) = hi;
            *(ushort4*)(Alo + row*72 + k4*4) = lo;
        }
        #pragma unroll
        for (int i = 0; i < 8; ++i) {
            const int idx = i*128 + t;
            const int kk = idx >> 4, n4 = idx & 15;
            const float4 v = *(const float4*)(Wl + (kbase + kt + kk)*64 + n4*4);
            const float vv[4] = {v.x, v.y, v.z, v.w};
            #pragma unroll
            for (int j = 0; j < 4; ++j) {
                float r;
                const unsigned short hh = bf_hi(vv[j], r);
                Bhi[(n4*4 + j)*72 + kk] = hh;
                Blo[(n4*4 + j)*72 + kk] = bf_rn(r);
            }
        }
        __syncthreads();

        #pragma unroll
        for (int ks = 0; ks < 4; ++ks) {
            uint32_t ah[4], al[4];
            ldm_x4(ah, sAhi + 2*(aRowA + ks*16));
            ldm_x4(al, sAlo + 2*(aRowA + ks*16));
            #pragma unroll
            for (int n = 0; n < 8; ++n) {
                uint32_t bh[2], bl[2];
                ldm_x2(bh, sBhi + 2*(aRowB + (uint32_t)(n*8*72) + ks*16));
                ldm_x2(bl, sBlo + 2*(aRowB + (uint32_t)(n*8*72) + ks*16));
                mma_bf16(acc[n], ah, bh);
                mma_bf16(acc[n], ah, bl);
                mma_bf16(acc[n], al, bh);
            }
        }
        __syncthreads();
    }

    const int row = lane >> 2, colp = (lane & 3)*2;
    const int m = r0 + w*16;
    float* pout = g_part + (size_t)blockIdx.y*NB*HL;
    #pragma unroll
    for (int n = 0; n < 8; ++n) {
        *(float2*)(pout + (size_t)(m + row    )*HL + n*8 + colp) = make_float2(acc[n][0], acc[n][1]);
        *(float2*)(pout + (size_t)(m + row + 8)*HL + n*8 + colp) = make_float2(acc[n][2], acc[n][3]);
    }
}

__global__ __launch_bounds__(256) void lin1_reduce(const float* __restrict__ b)
{
    const int idx = blockIdx.x*256 + threadIdx.x;
    float s = b[idx & 63];
    #pragma unroll
    for (int ks = 0; ks < KSPLIT; ++ks) s += g_part[(size_t)ks*NB*HL + idx];
    g_hid[idx] = fmaxf(s, 0.f);
}

// ---------------- head: hid @ lin2_W + b -> log_softmax ----------------
__global__ __launch_bounds__(64) void head_kernel(const float* __restrict__ W,
                                                  const float* __restrict__ bb,
                                                  float* __restrict__ out)
{
    const int g = blockIdx.x, t = threadIdx.x;
    const float v = g_hid[g*HL + t];
    float p0 = v * W[t*2 + 0];
    float p1 = v * W[t*2 + 1];
    #pragma unroll
    for (int o = 16; o; o >>= 1) {
        p0 += __shfl_down_sync(0xffffffffu, p0, o);
        p1 += __shfl_down_sync(0xffffffffu, p1, o);
    }
    __shared__ float s0[2], s1[2];
    if ((t & 31) == 0) { s0[t>>5] = p0; s1[t>>5] = p1; }
    __syncthreads();
    if (t == 0) {
        const float l0 = s0[0] + s0[1] + bb[0];
        const float l1 = s1[0] + s1[1] + bb[1];
        const float m = fmaxf(l0, l1);
        const float lse = m + logf(expf(l0 - m) + expf(l1 - m));
        out[g*2 + 0] = l0 - lse;
        out[g*2 + 1] = l1 - lse;
    }
}

// ---------------- launch ----------------
static const int PREPSMEM  = (90*96 + EPG + EPG + 90) * 4 + (90+91)*4 + EPG*2 + EPG;
static const int SMEM_C96  = 87040;   // conv_mma<96,48>
static const int SMEM_C128 = 97280;   // conv_mma<128,64>

extern "C" void kernel_launch(void* const* d_in, const int* in_sizes, int n_in,
                              void* d_out, int out_size)
{
    const float* x        = (const float*)d_in[0];
    const float* eattr    = (const float*)d_in[1];
    const float* W1       = (const float*)d_in[2];
    const float* b1       = (const float*)d_in[3];
    const float* W2       = (const float*)d_in[4];
    const float* b2       = (const float*)d_in[5];
    const float* W3       = (const float*)d_in[6];
    const float* b3       = (const float*)d_in[7];
    const float* lin1_W   = (const float*)d_in[8];
    const float* lin1_b   = (const float*)d_in[9];
    const float* lin2_W   = (const float*)d_in[10];
    const float* lin2_b   = (const float*)d_in[11];
    const void*  eindex   = d_in[12];
    float* out = (float*)d_out;

    float* zptr;
    cudaGetSymbolAddress((void**)&zptr, g_z);

    cudaFuncSetAttribute(prep_kernel,      cudaFuncAttributeMaxDynamicSharedMemorySize, PREPSMEM);
    cudaFuncSetAttribute(conv_mma<96,48>,  cudaFuncAttributeMaxDynamicSharedMemorySize, SMEM_C96);
    cudaFuncSetAttribute(conv_mma<128,64>, cudaFuncAttributeMaxDynamicSharedMemorySize, SMEM_C128);

    prep_kernel<<<NB, 256, PREPSMEM>>>(eindex, eattr);

    conv_mma<96,48> <<<dim3(NB,2), 256, SMEM_C96 >>>(x,    NODES*FIN, FIN,  90, 0,
                                                     W1, b1, 0);
    conv_mma<128,64><<<dim3(NB,2), 256, SMEM_C128>>>(zptr, ZW,        ZROW, 128, 0,
                                                     W2, b2, 128);
    conv_mma<128,64><<<dim3(NB,2), 256, SMEM_C128>>>(zptr, ZW,        ZROW, 128, 128,
                                                     W3, b3, 256);
    lin1_mma<<<dim3(8, KSPLIT), 128>>>(lin1_W);
    lin1_reduce<<<NB*HL/256, 256>>>(lin1_b);
    head_kernel<<<NB, 64>>>(lin2_W, lin2_b, out);
}